// round 16
// baseline (speedup 1.0000x reference)
#include <cuda_runtime.h>
#include <cuda_fp16.h>
#include <cstdint>

// ---------------- problem constants ----------------
#define KTOT 4096
#define NTOT 11008
#define MTOT 8192

#define MT 128
#define NT 128
#define BK 64
#define STAGES 3
#define THREADS 128                 // 4 warps -> 255-reg budget at 2 CTAs/SM
#define CHUNKS (KTOT / BK)          // 64

#define A_BYTES (MT * BK * 2)       // 16384
#define B_BYTES (NT * BK * 2)       // 16384
#define STAGE_BYTES (A_BYTES + B_BYTES)   // 32768
#define SMEM_STAGE0 1024            // mbarriers live below
#define SMEM_TOTAL (SMEM_STAGE0 + STAGES * STAGE_BYTES)  // 99328 -> 2 CTAs/SM

// ---------------- scratch (device globals, no allocs) ----------------
__device__ __align__(16) __half g_Xh[(size_t)MTOT * KTOT];   // 67 MB
__device__ __align__(16) __half g_Wh[(size_t)NTOT * KTOT];   // 90 MB

// ---------------- helpers ----------------
__device__ __forceinline__ uint32_t smem_u32(const void* p) {
    uint32_t a;
    asm("{ .reg .u64 t; cvta.to.shared.u64 t, %1; cvt.u32.u64 %0, t; }"
        : "=r"(a) : "l"(p));
    return a;
}
// 128-byte rows (64 fp16), 8 16B groups/row, XOR by (row&7):
// conflict-free for ldmatrix 8-row phases AND cp.async writes.
__device__ __forceinline__ uint32_t swz(int row, int g) {
    return (uint32_t)((row << 7) + (((g ^ (row & 7)) & 7) << 4));
}
__device__ __forceinline__ void cp16(uint32_t dst, const void* src) {
    asm volatile("cp.async.cg.shared.global [%0], [%1], 16;"
                 :: "r"(dst), "l"(src) : "memory");
}
__device__ __forceinline__ void mbar_init(uint32_t a, uint32_t n) {
    asm volatile("mbarrier.init.shared.b64 [%0], %1;" :: "r"(a), "r"(n) : "memory");
}
__device__ __forceinline__ void mbar_arrive(uint32_t a) {
    asm volatile("mbarrier.arrive.shared.b64 _, [%0];" :: "r"(a) : "memory");
}
// .noinc is load-bearing: the async arrive must consume the init count.
__device__ __forceinline__ void cpasync_arrive(uint32_t a) {
    asm volatile("cp.async.mbarrier.arrive.noinc.shared.b64 [%0];" :: "r"(a) : "memory");
}
__device__ __forceinline__ void mbar_wait(uint32_t mbar, uint32_t parity) {
    asm volatile(
        "{\n\t"
        ".reg .pred P;\n\t"
        "WL_%=:\n\t"
        "mbarrier.try_wait.parity.acquire.cta.shared::cta.b64 P, [%0], %1, 0x989680;\n\t"
        "@!P bra WL_%=;\n\t"
        "}" :: "r"(mbar), "r"(parity) : "memory");
}
__device__ __forceinline__ void ldsm4(uint32_t* r, uint32_t addr) {
    asm volatile("ldmatrix.sync.aligned.m8n8.x4.shared.b16 {%0,%1,%2,%3}, [%4];"
                 : "=r"(r[0]), "=r"(r[1]), "=r"(r[2]), "=r"(r[3]) : "r"(addr));
}
__device__ __forceinline__ void mma16816(float* c, const uint32_t* a,
                                         uint32_t b0, uint32_t b1) {
    asm volatile(
        "mma.sync.aligned.m16n8k16.row.col.f32.f16.f16.f32 "
        "{%0,%1,%2,%3}, {%4,%5,%6,%7}, {%8,%9}, {%0,%1,%2,%3};"
        : "+f"(c[0]), "+f"(c[1]), "+f"(c[2]), "+f"(c[3])
        : "r"(a[0]), "r"(a[1]), "r"(a[2]), "r"(a[3]), "r"(b0), "r"(b1));
}

// ---------------- fused prep kernel ----------------
#define PTHREADS 256
#define NK2 (NTOT * (KTOT / 2))          // 22,544,384
#define MK4 ((MTOT / 4) * KTOT)          // 8,388,608
__global__ void prep_kernel(const int* __restrict__ q, const float4* __restrict__ x) {
    size_t i = (size_t)blockIdx.x * PTHREADS + threadIdx.x;
    int v = q[i];
    int lo = (((v & 15) + 8) & 15) - 8;
    int hi = ((((v >> 4) & 15) + 8) & 15) - 8;
    __half2 w;
    w.x = __int2half_rn(lo);
    w.y = __int2half_rn(hi);
    reinterpret_cast<__half2*>(g_Wh)[i] = w;
    if (i < (size_t)MK4) {
        float4 xv = x[i];
        __half2* o = reinterpret_cast<__half2*>(g_Xh);
        o[2 * i]     = __floats2half2_rn(xv.x, xv.y);
        o[2 * i + 1] = __floats2half2_rn(xv.z, xv.w);
    }
}

// ---------------- GEMM ----------------
__device__ __forceinline__ void load_chunk(int c, int stage, uint32_t sb,
                                           const __half* Ag, const __half* Bg,
                                           int tid) {
    uint32_t s_a = sb + SMEM_STAGE0 + stage * STAGE_BYTES;
    uint32_t s_b = s_a + A_BYTES;
    const char* a = reinterpret_cast<const char*>(Ag) + (size_t)c * BK * 2;
    const char* b = reinterpret_cast<const char*>(Bg) + (size_t)c * BK * 2;
    const size_t rowb = (size_t)KTOT * 2;
#pragma unroll
    for (int i = 0; i < 8; i++) {            // A: 128 rows x 8 vecs
        int v = tid + i * THREADS;
        int row = v >> 3, g = v & 7;
        cp16(s_a + swz(row, g), a + (size_t)row * rowb + g * 16);
    }
#pragma unroll
    for (int i = 0; i < 8; i++) {            // B: 128 rows x 8 vecs
        int v = tid + i * THREADS;
        int row = v >> 3, g = v & 7;
        cp16(s_b + swz(row, g), b + (size_t)row * rowb + g * 16);
    }
}

// 64x64 warp tile: 4 A-frags + 4 B-frags per k16 step
__device__ __forceinline__ void load_frags(uint32_t sa, uint32_t sB, int kk,
                                           int wm, int wn, int lane,
                                           uint32_t af[4][4], uint32_t bf[4][4]) {
    int gg = kk * 2 + (lane >> 4);
#pragma unroll
    for (int mt = 0; mt < 4; mt++) {
        int row = wm + mt * 16 + (lane & 15);
        ldsm4(af[mt], sa + swz(row, gg));
    }
#pragma unroll
    for (int np = 0; np < 4; np++) {
        int row = wn + np * 16 + (lane & 15);
        ldsm4(bf[np], sB + swz(row, gg));
    }
}

__global__ void __launch_bounds__(THREADS, 2)
gemm_kernel(const float* __restrict__ scales, const float* __restrict__ bias,
            float* __restrict__ out) {
    extern __shared__ char smem[];
    uint32_t sb = smem_u32(smem);
    int tid = threadIdx.x, lane = tid & 31, wid = tid >> 5;

    // grouped rasterization (8 m-tiles per group) for L2 reuse of the W panel
    const int NTILES = NTOT / NT;   // 86
    const int GROUP = 8;
    int pid = blockIdx.x;
    int gsz = GROUP * NTILES;
    int g = pid / gsz, r = pid % gsz;
    int mtile = g * GROUP + (r % GROUP);
    int ntile = r / GROUP;
    int m0 = mtile * MT, n0 = ntile * NT;

    const __half* Ag = g_Xh + (size_t)m0 * KTOT;
    const __half* Bg = g_Wh + (size_t)n0 * KTOT;

    // warp grid: 2 (m) x 2 (n); warp tile 64x64
    const int wm = (wid >> 1) * 64;
    const int wn = (wid & 1) * 64;

    // mbarriers: full[s] at sb + 8s, empty[s] at sb + 24 + 8s
    if (tid == 0) {
#pragma unroll
        for (int s = 0; s < STAGES; s++) {
            mbar_init(sb + 8 * s, THREADS);        // full[s]
            mbar_init(sb + 24 + 8 * s, THREADS);   // empty[s]
        }
    }
    __syncthreads();   // publish mbarrier init (only block barrier here)

    float acc[4][8][4];
#pragma unroll
    for (int i = 0; i < 4; i++)
#pragma unroll
        for (int j = 0; j < 8; j++)
#pragma unroll
            for (int l = 0; l < 4; l++) acc[i][j][l] = 0.0f;

    // prologue: fill stages 0,1; async-arrive full on completion
    load_chunk(0, 0, sb, Ag, Bg, tid);
    cpasync_arrive(sb + 0);
    load_chunk(1, 1, sb, Ag, Bg, tid);
    cpasync_arrive(sb + 8);

    uint32_t af[2][4][4], bf[2][4][4];
    int cs = 0, cph = 0;       // consumer stage cursor / full-phase
    int ps = 2, pph = 1;       // producer stage cursor / empty-phase

    // preload chunk 0 step 0 fragments
    mbar_wait(sb + 0, 0);
    load_frags(sb + SMEM_STAGE0, sb + SMEM_STAGE0 + A_BYTES, 0, wm, wn, lane,
               af[0], bf[0]);

    for (int c = 0; c < CHUNKS; c++) {
        uint32_t sa = sb + SMEM_STAGE0 + cs * STAGE_BYTES;
        uint32_t sB = sa + A_BYTES;
        int ns  = (cs + 1 == STAGES) ? 0 : cs + 1;
        int nph = (cs + 1 == STAGES) ? (cph ^ 1) : cph;
#pragma unroll
        for (int j = 0; j < 4; j++) {              // 4 k16 steps per BK=64 chunk
            int cur = j & 1;
            if (j < 3)
                load_frags(sa, sB, j + 1, wm, wn, lane, af[cur ^ 1], bf[cur ^ 1]);
            if (j == 2)
                mbar_arrive(sb + 24 + 8 * cs);     // last read of stage cs issued
            if (j == 3 && c + 1 < CHUNKS) {
                // cross-chunk prefetch: step 0 of chunk c+1 (lands in af[0]/bf[0])
                mbar_wait(sb + 8 * ns, (uint32_t)nph);
                uint32_t na = sb + SMEM_STAGE0 + ns * STAGE_BYTES;
                load_frags(na, na + A_BYTES, 0, wm, wn, lane, af[cur ^ 1], bf[cur ^ 1]);
            }
#pragma unroll
            for (int mt = 0; mt < 4; mt++)
#pragma unroll
                for (int nt = 0; nt < 8; nt++)
                    mma16816(acc[mt][nt], af[cur][mt],
                             bf[cur][nt >> 1][nt & 1],
                             bf[cur][nt >> 1][(nt & 1) + 2]);
            if (j == 0) {
                int cn = c + 2;
                if (cn < CHUNKS) {
                    if (cn >= STAGES)              // stage reused: wait consumers
                        mbar_wait(sb + 24 + 8 * ps, (uint32_t)pph);
                    load_chunk(cn, ps, sb, Ag, Bg, tid);
                    cpasync_arrive(sb + 8 * ps);
                    ps++; if (ps == STAGES) { ps = 0; pph ^= 1; }
                }
            }
        }
        cs = ns; cph = nph;
    }

    // epilogue: scale (row-wise over N) + bias, fp32 stores
#pragma unroll
    for (int mt = 0; mt < 4; mt++) {
        int r0 = m0 + wm + mt * 16 + (lane >> 2);
        float* o0 = out + (size_t)r0 * NTOT;
        float* o1 = out + (size_t)(r0 + 8) * NTOT;
#pragma unroll
        for (int nt = 0; nt < 8; nt++) {
            int col = n0 + wn + nt * 8 + (lane & 3) * 2;
            float s0 = __ldg(scales + col), s1 = __ldg(scales + col + 1);
            float b0 = __ldg(bias + col),   b1 = __ldg(bias + col + 1);
            float2 v0, v1;
            v0.x = fmaf(acc[mt][nt][0], s0, b0);
            v0.y = fmaf(acc[mt][nt][1], s1, b1);
            v1.x = fmaf(acc[mt][nt][2], s0, b0);
            v1.y = fmaf(acc[mt][nt][3], s1, b1);
            *reinterpret_cast<float2*>(o0 + col) = v0;
            *reinterpret_cast<float2*>(o1 + col) = v1;
        }
    }
}

// ---------------- launch ----------------
extern "C" void kernel_launch(void* const* d_in, const int* in_sizes, int n_in,
                              void* d_out, int out_size) {
    const float* x      = (const float*)d_in[0];
    const int*   q      = (const int*)d_in[1];
    const float* scales = (const float*)d_in[2];
    const float* bias   = (const float*)d_in[3];
    float* out = (float*)d_out;

    prep_kernel<<<NK2 / PTHREADS, PTHREADS>>>(q, (const float4*)x);

    cudaFuncSetAttribute(gemm_kernel, cudaFuncAttributeMaxDynamicSharedMemorySize,
                         SMEM_TOTAL);
    gemm_kernel<<<(MTOT / MT) * (NTOT / NT), THREADS, SMEM_TOTAL>>>(scales, bias, out);
}

// round 17
// speedup vs baseline: 1.5660x; 1.5660x over previous
#include <cuda_runtime.h>
#include <cuda_fp16.h>
#include <cstdint>

// ---------------- problem constants ----------------
#define KTOT 4096
#define NTOT 11008
#define MTOT 8192

#define MT 128
#define NT 128
#define BK 64
#define STAGES 3
#define THREADS 128                 // 4 warps -> 255-reg budget at 2 CTAs/SM
#define CHUNKS (KTOT / BK)          // 64

#define A_BYTES (MT * BK * 2)       // 16384
#define B_BYTES (NT * BK * 2)       // 16384
#define STAGE_BYTES (A_BYTES + B_BYTES)   // 32768
#define SMEM_STAGE0 1024            // mbarriers live below
#define SMEM_TOTAL (SMEM_STAGE0 + STAGES * STAGE_BYTES)  // 99328 -> 2 CTAs/SM

// ---------------- scratch (device globals, no allocs) ----------------
__device__ __align__(16) __half g_Xh[(size_t)MTOT * KTOT];   // 67 MB
__device__ __align__(16) __half g_Wh[(size_t)NTOT * KTOT];   // 90 MB

// ---------------- helpers ----------------
__device__ __forceinline__ uint32_t smem_u32(const void* p) {
    uint32_t a;
    asm("{ .reg .u64 t; cvta.to.shared.u64 t, %1; cvt.u32.u64 %0, t; }"
        : "=r"(a) : "l"(p));
    return a;
}
__device__ __forceinline__ void cp16(uint32_t dst, const void* src) {
    asm volatile("cp.async.cg.shared.global [%0], [%1], 16;"
                 :: "r"(dst), "l"(src) : "memory");
}
__device__ __forceinline__ void mbar_init(uint32_t a, uint32_t n) {
    asm volatile("mbarrier.init.shared.b64 [%0], %1;" :: "r"(a), "r"(n) : "memory");
}
__device__ __forceinline__ void mbar_arrive(uint32_t a) {
    asm volatile("mbarrier.arrive.shared.b64 _, [%0];" :: "r"(a) : "memory");
}
// .noinc is load-bearing: the async arrive must consume the init count.
__device__ __forceinline__ void cpasync_arrive(uint32_t a) {
    asm volatile("cp.async.mbarrier.arrive.noinc.shared.b64 [%0];" :: "r"(a) : "memory");
}
__device__ __forceinline__ void mbar_wait(uint32_t mbar, uint32_t parity) {
    asm volatile(
        "{\n\t"
        ".reg .pred P;\n\t"
        "WL_%=:\n\t"
        "mbarrier.try_wait.parity.acquire.cta.shared::cta.b64 P, [%0], %1, 0x989680;\n\t"
        "@!P bra WL_%=;\n\t"
        "}" :: "r"(mbar), "r"(parity) : "memory");
}
__device__ __forceinline__ void ldsm4(uint32_t* r, uint32_t addr) {
    asm volatile("ldmatrix.sync.aligned.m8n8.x4.shared.b16 {%0,%1,%2,%3}, [%4];"
                 : "=r"(r[0]), "=r"(r[1]), "=r"(r[2]), "=r"(r[3]) : "r"(addr));
}
__device__ __forceinline__ void mma16816(float* c, const uint32_t* a,
                                         uint32_t b0, uint32_t b1) {
    asm volatile(
        "mma.sync.aligned.m16n8k16.row.col.f32.f16.f16.f32 "
        "{%0,%1,%2,%3}, {%4,%5,%6,%7}, {%8,%9}, {%0,%1,%2,%3};"
        : "+f"(c[0]), "+f"(c[1]), "+f"(c[2]), "+f"(c[3])
        : "r"(a[0]), "r"(a[1]), "r"(a[2]), "r"(a[3]), "r"(b0), "r"(b1));
}

// ---------------- fused prep kernel ----------------
#define PTHREADS 256
#define NK2 (NTOT * (KTOT / 2))          // 22,544,384
#define MK4 ((MTOT / 4) * KTOT)          // 8,388,608
__global__ void prep_kernel(const int* __restrict__ q, const float4* __restrict__ x) {
    size_t i = (size_t)blockIdx.x * PTHREADS + threadIdx.x;
    int v = q[i];
    int lo = (((v & 15) + 8) & 15) - 8;
    int hi = ((((v >> 4) & 15) + 8) & 15) - 8;
    __half2 w;
    w.x = __int2half_rn(lo);
    w.y = __int2half_rn(hi);
    reinterpret_cast<__half2*>(g_Wh)[i] = w;
    if (i < (size_t)MK4) {
        float4 xv = x[i];
        __half2* o = reinterpret_cast<__half2*>(g_Xh);
        o[2 * i]     = __floats2half2_rn(xv.x, xv.y);
        o[2 * i + 1] = __floats2half2_rn(xv.z, xv.w);
    }
}

// ---------------- GEMM ----------------
// XOR-linear swizzle: swz(row,g) = (row<<7) | (((g ^ (row&7))&7)<<4) and the
// g-term never carries, so addr(kk,mt) = (sa + base) ^ (kk<<5) + mt*2048 with
// base = (row0<<7) | (((lane&7) ^ g0)<<4).  One register per operand.
__device__ __forceinline__ void load_frags(uint32_t pA, uint32_t pB, int kk,
                                           uint32_t af[4][4], uint32_t bf[4][4]) {
    uint32_t tA = pA ^ (uint32_t)(kk << 5);
    uint32_t tB = pB ^ (uint32_t)(kk << 5);
#pragma unroll
    for (int mt = 0; mt < 4; mt++) ldsm4(af[mt], tA + mt * 2048);
#pragma unroll
    for (int np = 0; np < 4; np++) ldsm4(bf[np], tB + np * 2048);
}

__global__ void __launch_bounds__(THREADS, 2)
gemm_kernel(const float* __restrict__ scales, const float* __restrict__ bias,
            float* __restrict__ out) {
    extern __shared__ char smem[];
    uint32_t sb = smem_u32(smem);
    int tid = threadIdx.x, lane = tid & 31, wid = tid >> 5;

    // grouped rasterization (8 m-tiles per group) for L2 reuse of the W panel
    const int NTILES = NTOT / NT;   // 86
    const int GROUP = 8;
    int pid = blockIdx.x;
    int gsz = GROUP * NTILES;
    int g = pid / gsz, r = pid % gsz;
    int mtile = g * GROUP + (r % GROUP);
    int ntile = r / GROUP;
    int m0 = mtile * MT, n0 = ntile * NT;

    // warp grid: 2 (m) x 2 (n); warp tile 64x64
    const int wm = (wid >> 1) * 64;
    const int wn = (wid & 1) * 64;

    // ldsm per-lane folded bases (g0 = lane>>4 pre-XORed into bits 4-6)
    const uint32_t xorg = (uint32_t)(((lane & 7) ^ (lane >> 4)) << 4);
    const uint32_t fA = ((uint32_t)(wm + (lane & 15)) << 7) + xorg;
    const uint32_t fB = ((uint32_t)(wn + (lane & 15)) << 7) + xorg;

    // cp.async per-thread bases: 16 rows per i-step, 8192 B per gmem row
    const uint32_t dstRel = ((uint32_t)(tid >> 3) << 7)
                          + ((uint32_t)(((tid & 7) ^ ((tid >> 3) & 7))) << 4);
    const char* aSrc = reinterpret_cast<const char*>(g_Xh + (size_t)m0 * KTOT)
                     + (size_t)(tid >> 3) * (KTOT * 2) + (size_t)(tid & 7) * 16;
    const char* bSrc = reinterpret_cast<const char*>(g_Wh + (size_t)n0 * KTOT)
                     + (size_t)(tid >> 3) * (KTOT * 2) + (size_t)(tid & 7) * 16;

    // mbarriers: full[s] at sb + 8s, empty[s] at sb + 24 + 8s
    if (tid == 0) {
#pragma unroll
        for (int s = 0; s < STAGES; s++) {
            mbar_init(sb + 8 * s, THREADS);        // full[s]
            mbar_init(sb + 24 + 8 * s, THREADS);   // empty[s]
        }
    }
    __syncthreads();   // publish mbarrier init (only block barrier here)

    float acc[4][8][4];
#pragma unroll
    for (int i = 0; i < 4; i++)
#pragma unroll
        for (int j = 0; j < 8; j++)
#pragma unroll
            for (int l = 0; l < 4; l++) acc[i][j][l] = 0.0f;

    // producer body: chunk c into stage st
    auto load_chunk = [&](int c, int st) {
        uint32_t s_a = sb + SMEM_STAGE0 + st * STAGE_BYTES + dstRel;
        const char* a = aSrc + (size_t)c * (BK * 2);
        const char* b = bSrc + (size_t)c * (BK * 2);
#pragma unroll
        for (int i = 0; i < 8; i++) {
            cp16(s_a + i * 2048,           a + (size_t)i * (16 * KTOT * 2));
            cp16(s_a + A_BYTES + i * 2048, b + (size_t)i * (16 * KTOT * 2));
        }
    };

    // prologue: fill stages 0,1; async-arrive full on completion
    load_chunk(0, 0);
    cpasync_arrive(sb + 0);
    load_chunk(1, 1);
    cpasync_arrive(sb + 8);

    uint32_t af[2][4][4], bf[2][4][4];
    int cs = 0, cph = 0;       // consumer stage cursor / full-phase
    int ps = 2, pph = 1;       // producer stage cursor / empty-phase

    // preload chunk 0 step 0 fragments
    mbar_wait(sb + 0, 0);
    load_frags(sb + SMEM_STAGE0 + fA, sb + SMEM_STAGE0 + A_BYTES + fB, 0,
               af[0], bf[0]);

    for (int c = 0; c < CHUNKS; c++) {
        uint32_t sa = sb + SMEM_STAGE0 + cs * STAGE_BYTES;
        uint32_t pA = sa + fA;
        uint32_t pB = sa + A_BYTES + fB;
        int ns  = (cs + 1 == STAGES) ? 0 : cs + 1;
        int nph = (cs + 1 == STAGES) ? (cph ^ 1) : cph;
#pragma unroll
        for (int j = 0; j < 4; j++) {              // 4 k16 steps per BK=64 chunk
            int cur = j & 1;
            if (j < 3)
                load_frags(pA, pB, j + 1, af[cur ^ 1], bf[cur ^ 1]);
            if (j == 2)
                mbar_arrive(sb + 24 + 8 * cs);     // last read of stage cs issued
            if (j == 3 && c + 1 < CHUNKS) {
                // cross-chunk prefetch: step 0 of chunk c+1 (lands in af[0]/bf[0])
                mbar_wait(sb + 8 * ns, (uint32_t)nph);
                uint32_t na = sb + SMEM_STAGE0 + ns * STAGE_BYTES;
                load_frags(na + fA, na + A_BYTES + fB, 0, af[cur ^ 1], bf[cur ^ 1]);
            }
#pragma unroll
            for (int mt = 0; mt < 4; mt++)
#pragma unroll
                for (int nt = 0; nt < 8; nt++)
                    mma16816(acc[mt][nt], af[cur][mt],
                             bf[cur][nt >> 1][nt & 1],
                             bf[cur][nt >> 1][(nt & 1) + 2]);
            if (j == 0) {
                int cn = c + 2;
                if (cn < CHUNKS) {
                    if (cn >= STAGES)              // stage reused: wait consumers
                        mbar_wait(sb + 24 + 8 * ps, (uint32_t)pph);
                    load_chunk(cn, ps);
                    cpasync_arrive(sb + 8 * ps);
                    ps++; if (ps == STAGES) { ps = 0; pph ^= 1; }
                }
            }
        }
        cs = ns; cph = nph;
    }

    // epilogue: scale (row-wise over N) + bias, fp32 stores
#pragma unroll
    for (int mt = 0; mt < 4; mt++) {
        int r0 = m0 + wm + mt * 16 + (lane >> 2);
        float* o0 = out + (size_t)r0 * NTOT;
        float* o1 = out + (size_t)(r0 + 8) * NTOT;
#pragma unroll
        for (int nt = 0; nt < 8; nt++) {
            int col = n0 + wn + nt * 8 + (lane & 3) * 2;
            float s0 = __ldg(scales + col), s1 = __ldg(scales + col + 1);
            float b0 = __ldg(bias + col),   b1 = __ldg(bias + col + 1);
            float2 v0, v1;
            v0.x = fmaf(acc[mt][nt][0], s0, b0);
            v0.y = fmaf(acc[mt][nt][1], s1, b1);
            v1.x = fmaf(acc[mt][nt][2], s0, b0);
            v1.y = fmaf(acc[mt][nt][3], s1, b1);
            *reinterpret_cast<float2*>(o0 + col) = v0;
            *reinterpret_cast<float2*>(o1 + col) = v1;
        }
    }
}

// ---------------- launch ----------------
extern "C" void kernel_launch(void* const* d_in, const int* in_sizes, int n_in,
                              void* d_out, int out_size) {
    const float* x      = (const float*)d_in[0];
    const int*   q      = (const int*)d_in[1];
    const float* scales = (const float*)d_in[2];
    const float* bias   = (const float*)d_in[3];
    float* out = (float*)d_out;

    prep_kernel<<<NK2 / PTHREADS, PTHREADS>>>(q, (const float4*)x);

    cudaFuncSetAttribute(gemm_kernel, cudaFuncAttributeMaxDynamicSharedMemorySize,
                         SMEM_TOTAL);
    gemm_kernel<<<(MTOT / MT) * (NTOT / NT), THREADS, SMEM_TOTAL>>>(scales, bias, out);
}